// round 3
// baseline (speedup 1.0000x reference)
#include <cuda_runtime.h>

// QuantumConvLayer: out[:,2i]   = cos(q[2i]) * cos(pi*x[:,2i])
//                   out[:,2i+1] = out[:,2i]  * cos(q[2i+1] + pi*x[:,2i+1])
// Streaming HBM-bound (256MB read + 256MB write).
// R3: 4x float4 per thread, ALL loads front-batched (raise per-SM in-flight
// bytes), all stores batched at the end (longer same-direction DRAM bursts).

#ifndef QC_PI
#define QC_PI 3.14159265358979323846f
#endif

__global__ void __launch_bounds__(256, 8)
qconv_kernel(const float4* __restrict__ x4,
             const float*  __restrict__ q,
             float4* __restrict__ out4,
             int n4)
{
    int t = blockIdx.x * blockDim.x + threadIdx.x;
    int j = t << 2;                 // first float4 index (4 per thread)
    if (j >= n4) return;

    // 4 back-to-back 128-bit streaming loads — 64B in flight per thread
    float4 v0 = __ldcs(x4 + j);
    float4 v1 = __ldcs(x4 + j + 1);
    float4 v2 = __ldcs(x4 + j + 2);
    float4 v3 = __ldcs(x4 + j + 3);

    // j is a multiple of 4 -> v0.x column is 0 or 8; 4 float4s cover exactly
    // one full 16-wide row (c=0) or wrap 8..15,0..7 — but since rows are 16
    // floats and j*4 % 16 is 0 or 8, the q pairs per float4 are:
    int c = (j << 2) & 15;          // 0 or 8
    const float4* q4 = (const float4*)q;
    float4 qa = __ldg(q4 + ((c >> 2) + 0));        // pairs for v0
    float4 qb = __ldg(q4 + ((c >> 2) + 1));        // pairs for v1
    float4 qc = __ldg(q4 + (((c >> 2) + 2) & 3));  // pairs for v2 (wraps)
    float4 qd = __ldg(q4 + (((c >> 2) + 3) & 3));  // pairs for v3 (wraps)

    float ze0 = __cosf(qa.x) * __cosf(QC_PI * v0.x);
    float zo0 = ze0 * __cosf(fmaf(QC_PI, v0.y, qa.y));
    float ze1 = __cosf(qa.z) * __cosf(QC_PI * v0.z);
    float zo1 = ze1 * __cosf(fmaf(QC_PI, v0.w, qa.w));

    float ze2 = __cosf(qb.x) * __cosf(QC_PI * v1.x);
    float zo2 = ze2 * __cosf(fmaf(QC_PI, v1.y, qb.y));
    float ze3 = __cosf(qb.z) * __cosf(QC_PI * v1.z);
    float zo3 = ze3 * __cosf(fmaf(QC_PI, v1.w, qb.w));

    float ze4 = __cosf(qc.x) * __cosf(QC_PI * v2.x);
    float zo4 = ze4 * __cosf(fmaf(QC_PI, v2.y, qc.y));
    float ze5 = __cosf(qc.z) * __cosf(QC_PI * v2.z);
    float zo5 = ze5 * __cosf(fmaf(QC_PI, v2.w, qc.w));

    float ze6 = __cosf(qd.x) * __cosf(QC_PI * v3.x);
    float zo6 = ze6 * __cosf(fmaf(QC_PI, v3.y, qd.y));
    float ze7 = __cosf(qd.z) * __cosf(QC_PI * v3.z);
    float zo7 = ze7 * __cosf(fmaf(QC_PI, v3.w, qd.w));

    // 4 back-to-back 128-bit streaming stores
    __stcs(out4 + j,     make_float4(ze0, zo0, ze1, zo1));
    __stcs(out4 + j + 1, make_float4(ze2, zo2, ze3, zo3));
    __stcs(out4 + j + 2, make_float4(ze4, zo4, ze5, zo5));
    __stcs(out4 + j + 3, make_float4(ze6, zo6, ze7, zo7));
}

extern "C" void kernel_launch(void* const* d_in, const int* in_sizes, int n_in,
                              void* d_out, int out_size)
{
    const float4* x4 = (const float4*)d_in[0];
    const float*  q  = (const float*)d_in[1];
    float4* out4     = (float4*)d_out;

    int n_elems = in_sizes[0];   // B * 16 = 67108864
    int n4 = n_elems >> 2;       // 16777216 float4s
    int nthreads = n4 >> 2;      // 4 float4s per thread

    int threads = 256;
    int blocks  = (nthreads + threads - 1) / threads;
    qconv_kernel<<<blocks, threads>>>(x4, q, out4, n4);
}

// round 4
// speedup vs baseline: 1.2257x; 1.2257x over previous
#include <cuda_runtime.h>

// QuantumConvLayer: out[:,2i]   = cos(q[2i]) * cos(pi*x[:,2i])
//                   out[:,2i+1] = out[:,2i]  * cos(q[2i+1] + pi*x[:,2i+1])
// Streaming HBM-bound (256MB read + 256MB write).
// R4: 4 float4/thread with BLOCK-STRIDED addressing — every LDG.128 stays
// fully warp-coalesced (R3 broke this) while per-thread MLP=4 raises the
// per-SM in-flight byte pool. Stride 256 float4s keeps the q-row phase
// identical across the 4 elements -> single q float4 load per thread.

#ifndef QC_PI
#define QC_PI 3.14159265358979323846f
#endif

#define VPT 4   // float4s per thread
#define TPB 256 // threads per block

__global__ void __launch_bounds__(TPB, 6)
qconv_kernel(const float4* __restrict__ x4,
             const float*  __restrict__ q,
             float4* __restrict__ out4,
             int n4)
{
    int base = blockIdx.x * (TPB * VPT) + threadIdx.x;

    // 4 coalesced 128-bit streaming loads, front-batched (MLP=4)
    float4 v0, v1, v2, v3;
    bool g0 = base + 0 * TPB < n4;
    bool g1 = base + 1 * TPB < n4;
    bool g2 = base + 2 * TPB < n4;
    bool g3 = base + 3 * TPB < n4;
    if (g0) v0 = __ldcs(x4 + base + 0 * TPB);
    if (g1) v1 = __ldcs(x4 + base + 1 * TPB);
    if (g2) v2 = __ldcs(x4 + base + 2 * TPB);
    if (g3) v3 = __ldcs(x4 + base + 3 * TPB);

    // row phase: float4 index `i` covers columns (4i..4i+3) mod 16.
    // stride TPB=256 is 0 mod 4, so all 4 elements share (base & 3).
    const float4* q4 = (const float4*)q;
    float4 qa = __ldg(q4 + (base & 3));   // q[c..c+3], c = 4*(base&3)

    float ce = __cosf(qa.x);   // cos(q[c])
    float cf = __cosf(qa.z);   // cos(q[c+2])

    if (g0) {
        float ze0 = ce * __cosf(QC_PI * v0.x);
        float zo0 = ze0 * __cosf(fmaf(QC_PI, v0.y, qa.y));
        float ze1 = cf * __cosf(QC_PI * v0.z);
        float zo1 = ze1 * __cosf(fmaf(QC_PI, v0.w, qa.w));
        __stcs(out4 + base + 0 * TPB, make_float4(ze0, zo0, ze1, zo1));
    }
    if (g1) {
        float ze0 = ce * __cosf(QC_PI * v1.x);
        float zo0 = ze0 * __cosf(fmaf(QC_PI, v1.y, qa.y));
        float ze1 = cf * __cosf(QC_PI * v1.z);
        float zo1 = ze1 * __cosf(fmaf(QC_PI, v1.w, qa.w));
        __stcs(out4 + base + 1 * TPB, make_float4(ze0, zo0, ze1, zo1));
    }
    if (g2) {
        float ze0 = ce * __cosf(QC_PI * v2.x);
        float zo0 = ze0 * __cosf(fmaf(QC_PI, v2.y, qa.y));
        float ze1 = cf * __cosf(QC_PI * v2.z);
        float zo1 = ze1 * __cosf(fmaf(QC_PI, v2.w, qa.w));
        __stcs(out4 + base + 2 * TPB, make_float4(ze0, zo0, ze1, zo1));
    }
    if (g3) {
        float ze0 = ce * __cosf(QC_PI * v3.x);
        float zo0 = ze0 * __cosf(fmaf(QC_PI, v3.y, qa.y));
        float ze1 = cf * __cosf(QC_PI * v3.z);
        float zo1 = ze1 * __cosf(fmaf(QC_PI, v3.w, qa.w));
        __stcs(out4 + base + 3 * TPB, make_float4(ze0, zo0, ze1, zo1));
    }
}

extern "C" void kernel_launch(void* const* d_in, const int* in_sizes, int n_in,
                              void* d_out, int out_size)
{
    const float4* x4 = (const float4*)d_in[0];
    const float*  q  = (const float*)d_in[1];
    float4* out4     = (float4*)d_out;

    int n_elems = in_sizes[0];   // B * 16 = 67108864
    int n4 = n_elems >> 2;       // 16777216 float4s

    int per_block = TPB * VPT;   // 1024 float4s per block
    int blocks = (n4 + per_block - 1) / per_block;
    qconv_kernel<<<blocks, TPB>>>(x4, q, out4, n4);
}